// round 12
// baseline (speedup 1.0000x reference)
#include <cuda_runtime.h>
#include <stdint.h>

// BNB 8-bit embedding dequant gather (harness materializes int8 q_weight as int32):
//   out[token,:] = (float)q_weight[x[token],:] * (absmax[x[token]] / 127)
// x[32768] i32, q_weight[50257,1024] i32, absmax[50257] f32, out[32768,1024] f32.
//
// R10 kernel (best: 4 tokens/CTA, 256 thr, int4 gathers, __stwt stores) with
// ONE change: table gathers carry an L2::evict_last cache-policy via
// createpolicy + ld.global.nc.L2::cache_hint (works at 16B width, unlike the
// direct .L2::evict_last modifier). Goal: raise cross-graph-replay L2
// retention of the ~96MB touched table -> fewer DRAM reads.

static constexpr int DIM = 1024;
static constexpr int THREADS = 256;        // DIM/4 int4 lanes
static constexpr int TOKENS_PER_CTA = 4;

__device__ __forceinline__ uint64_t make_evict_last_policy() {
    uint64_t pol;
    asm volatile("createpolicy.fractional.L2::evict_last.b64 %0, 1.0;"
                 : "=l"(pol));
    return pol;
}

__device__ __forceinline__ int4 ldg_hint(const int4* p, uint64_t pol) {
    int4 v;
    asm volatile("ld.global.nc.L2::cache_hint.v4.b32 {%0,%1,%2,%3}, [%4], %5;"
                 : "=r"(v.x), "=r"(v.y), "=r"(v.z), "=r"(v.w)
                 : "l"(p), "l"(pol));
    return v;
}

__global__ __launch_bounds__(THREADS, 8)
void bnb8_embed_kernel(const int* __restrict__ x,
                       const int* __restrict__ qw,
                       const float* __restrict__ absmax,
                       float* __restrict__ out,
                       int n_tokens)
{
    const int base = blockIdx.x * TOKENS_PER_CTA;
    const uint64_t pol = make_evict_last_policy();

    // Broadcast index loads (same addr across CTA -> 1 request + broadcast).
    int rows[TOKENS_PER_CTA];
#pragma unroll
    for (int i = 0; i < TOKENS_PER_CTA; i++)
        rows[i] = __ldg(x + base + i);

    float scales[TOKENS_PER_CTA];
#pragma unroll
    for (int i = 0; i < TOKENS_PER_CTA; i++)
        scales[i] = __ldg(absmax + rows[i]) * (1.0f / 127.0f);

    // 4 independent 16B gathers in flight; evict_last policy pins table in L2.
    int4 v[TOKENS_PER_CTA];
#pragma unroll
    for (int i = 0; i < TOKENS_PER_CTA; i++) {
        const int4* rp = reinterpret_cast<const int4*>(qw + (long long)rows[i] * DIM);
        v[i] = ldg_hint(rp + threadIdx.x, pol);
    }

#pragma unroll
    for (int i = 0; i < TOKENS_PER_CTA; i++) {
        float4 o;
        o.x = (float)v[i].x * scales[i];
        o.y = (float)v[i].y * scales[i];
        o.z = (float)v[i].z * scales[i];
        o.w = (float)v[i].w * scales[i];
        float4* op = reinterpret_cast<float4*>(out + (long long)(base + i) * DIM);
        __stwt(op + threadIdx.x, o);   // write-through: don't displace table in L2
    }
}

extern "C" void kernel_launch(void* const* d_in, const int* in_sizes, int n_in,
                              void* d_out, int out_size)
{
    // Bind by element count: qw largest, x smallest, absmax the remaining one.
    long long max_sz = -1;
    int qw_idx = -1;
    for (int i = 0; i < n_in; i++)
        if ((long long)in_sizes[i] > max_sz) { max_sz = in_sizes[i]; qw_idx = i; }

    long long min_sz = 0x7fffffffffffLL;
    int x_idx = -1;
    for (int i = 0; i < n_in; i++) {
        if (i == qw_idx) continue;
        if ((long long)in_sizes[i] < min_sz) { min_sz = in_sizes[i]; x_idx = i; }
    }
    int am_idx = -1;
    for (int i = 0; i < n_in; i++)
        if (i != qw_idx && i != x_idx) am_idx = i;

    const int*   x      = (const int*)d_in[x_idx];
    const int*   qw     = (const int*)d_in[qw_idx];
    const float* absmax = (const float*)d_in[am_idx];
    float*       out    = (float*)d_out;
    const int n_tokens  = in_sizes[x_idx];  // 32768

    const int grid = (n_tokens + TOKENS_PER_CTA - 1) / TOKENS_PER_CTA;
    bnb8_embed_kernel<<<grid, THREADS>>>(x, qw, absmax, out, n_tokens);
}

// round 13
// speedup vs baseline: 1.0312x; 1.0312x over previous
#include <cuda_runtime.h>
#include <stdint.h>

// BNB 8-bit embedding dequant gather (harness materializes int8 q_weight as int32):
//   out[token,:] = (float)q_weight[x[token],:] * (absmax[x[token]] / 127)
// x[32768] i32, q_weight[50257,1024] i32, absmax[50257] f32, out[32768,1024] f32.
//
// FINAL SHAPE (session best kernel time, 35.78us):
//   - 4 tokens/CTA, 256 threads, one int4 (16B) gather lane per thread
//   - 4 independent gathers in flight per thread (MLP=4) before any consume
//   - no barriers; index loads are CTA-wide broadcasts
//   - __stwt output stores: write-through, don't displace table lines in L2
// Verified dead ends: higher MLP (reg-capped or occupancy-priced), persistent
// pipelining, evict_last policies (both encodings) — all neutral or slower.
// The kernel runs at the mixed random-read + streaming-write DRAM ceiling.

static constexpr int DIM = 1024;
static constexpr int THREADS = 256;        // DIM/4 int4 lanes
static constexpr int TOKENS_PER_CTA = 4;

__global__ __launch_bounds__(THREADS, 8)
void bnb8_embed_kernel(const int* __restrict__ x,
                       const int* __restrict__ qw,
                       const float* __restrict__ absmax,
                       float* __restrict__ out,
                       int n_tokens)
{
    const int base = blockIdx.x * TOKENS_PER_CTA;

    // Broadcast index loads (same addr across CTA -> 1 request + broadcast).
    int rows[TOKENS_PER_CTA];
#pragma unroll
    for (int i = 0; i < TOKENS_PER_CTA; i++)
        rows[i] = __ldg(x + base + i);

    float scales[TOKENS_PER_CTA];
#pragma unroll
    for (int i = 0; i < TOKENS_PER_CTA; i++)
        scales[i] = __ldg(absmax + rows[i]) * (1.0f / 127.0f);

    // 4 independent 16B gathers in flight before any consumption.
    int4 v[TOKENS_PER_CTA];
#pragma unroll
    for (int i = 0; i < TOKENS_PER_CTA; i++) {
        const int4* rp = reinterpret_cast<const int4*>(qw + (long long)rows[i] * DIM);
        v[i] = __ldg(rp + threadIdx.x);
    }

#pragma unroll
    for (int i = 0; i < TOKENS_PER_CTA; i++) {
        float4 o;
        o.x = (float)v[i].x * scales[i];
        o.y = (float)v[i].y * scales[i];
        o.z = (float)v[i].z * scales[i];
        o.w = (float)v[i].w * scales[i];
        float4* op = reinterpret_cast<float4*>(out + (long long)(base + i) * DIM);
        __stwt(op + threadIdx.x, o);   // write-through: don't displace table in L2
    }
}

extern "C" void kernel_launch(void* const* d_in, const int* in_sizes, int n_in,
                              void* d_out, int out_size)
{
    // Bind by element count: qw largest, x smallest, absmax the remaining one.
    long long max_sz = -1;
    int qw_idx = -1;
    for (int i = 0; i < n_in; i++)
        if ((long long)in_sizes[i] > max_sz) { max_sz = in_sizes[i]; qw_idx = i; }

    long long min_sz = 0x7fffffffffffLL;
    int x_idx = -1;
    for (int i = 0; i < n_in; i++) {
        if (i == qw_idx) continue;
        if ((long long)in_sizes[i] < min_sz) { min_sz = in_sizes[i]; x_idx = i; }
    }
    int am_idx = -1;
    for (int i = 0; i < n_in; i++)
        if (i != qw_idx && i != x_idx) am_idx = i;

    const int*   x      = (const int*)d_in[x_idx];
    const int*   qw     = (const int*)d_in[qw_idx];
    const float* absmax = (const float*)d_in[am_idx];
    float*       out    = (float*)d_out;
    const int n_tokens  = in_sizes[x_idx];  // 32768

    const int grid = (n_tokens + TOKENS_PER_CTA - 1) / TOKENS_PER_CTA;
    bnb8_embed_kernel<<<grid, THREADS>>>(x, qw, absmax, out, n_tokens);
}

// round 14
// speedup vs baseline: 1.0718x; 1.0394x over previous
#include <cuda_runtime.h>
#include <stdint.h>

// BNB 8-bit embedding dequant gather (harness materializes int8 q_weight as int32):
//   out[token,:] = (float)q_weight[x[token],:] * (absmax[x[token]] / 127)
// x[32768] i32, q_weight[50257,1024] i32, absmax[50257] f32, out[32768,1024] f32.
//
// FINAL (session-best dur 42.0us, kernel ~36.1us @ DRAM 66%):
//   - 4 tokens/CTA, 256 threads, one int4 (16B) gather lane per thread
//   - 4 independent gathers in flight per thread (MLP=4) before any consume
//   - no barriers; index loads are CTA-wide broadcasts
//   - __stcs output stores (evict-first). NOT __stwt: write-through drains at
//     kernel end and costs ~1us of replay wall time despite equal ncu time.
// Falsified levers: MLP>4, persistent pipelining, evict_last (2 encodings),
// 32B policy lanes, write-through. Kernel sits at the mixed random-read +
// streaming-write DRAM ceiling (~5.3TB/s on ~193MB/replay).

static constexpr int DIM = 1024;
static constexpr int THREADS = 256;        // DIM/4 int4 lanes
static constexpr int TOKENS_PER_CTA = 4;

__global__ __launch_bounds__(THREADS, 8)
void bnb8_embed_kernel(const int* __restrict__ x,
                       const int* __restrict__ qw,
                       const float* __restrict__ absmax,
                       float* __restrict__ out,
                       int n_tokens)
{
    const int base = blockIdx.x * TOKENS_PER_CTA;

    // Broadcast index loads (same addr across CTA -> 1 request + broadcast).
    int rows[TOKENS_PER_CTA];
#pragma unroll
    for (int i = 0; i < TOKENS_PER_CTA; i++)
        rows[i] = __ldg(x + base + i);

    float scales[TOKENS_PER_CTA];
#pragma unroll
    for (int i = 0; i < TOKENS_PER_CTA; i++)
        scales[i] = __ldg(absmax + rows[i]) * (1.0f / 127.0f);

    // 4 independent 16B gathers in flight before any consumption.
    int4 v[TOKENS_PER_CTA];
#pragma unroll
    for (int i = 0; i < TOKENS_PER_CTA; i++) {
        const int4* rp = reinterpret_cast<const int4*>(qw + (long long)rows[i] * DIM);
        v[i] = __ldg(rp + threadIdx.x);
    }

#pragma unroll
    for (int i = 0; i < TOKENS_PER_CTA; i++) {
        float4 o;
        o.x = (float)v[i].x * scales[i];
        o.y = (float)v[i].y * scales[i];
        o.z = (float)v[i].z * scales[i];
        o.w = (float)v[i].w * scales[i];
        float4* op = reinterpret_cast<float4*>(out + (long long)(base + i) * DIM);
        __stcs(op + threadIdx.x, o);   // evict-first: output never re-read
    }
}

extern "C" void kernel_launch(void* const* d_in, const int* in_sizes, int n_in,
                              void* d_out, int out_size)
{
    // Bind by element count: qw largest, x smallest, absmax the remaining one.
    long long max_sz = -1;
    int qw_idx = -1;
    for (int i = 0; i < n_in; i++)
        if ((long long)in_sizes[i] > max_sz) { max_sz = in_sizes[i]; qw_idx = i; }

    long long min_sz = 0x7fffffffffffLL;
    int x_idx = -1;
    for (int i = 0; i < n_in; i++) {
        if (i == qw_idx) continue;
        if ((long long)in_sizes[i] < min_sz) { min_sz = in_sizes[i]; x_idx = i; }
    }
    int am_idx = -1;
    for (int i = 0; i < n_in; i++)
        if (i != qw_idx && i != x_idx) am_idx = i;

    const int*   x      = (const int*)d_in[x_idx];
    const int*   qw     = (const int*)d_in[qw_idx];
    const float* absmax = (const float*)d_in[am_idx];
    float*       out    = (float*)d_out;
    const int n_tokens  = in_sizes[x_idx];  // 32768

    const int grid = (n_tokens + TOKENS_PER_CTA - 1) / TOKENS_PER_CTA;
    bnb8_embed_kernel<<<grid, THREADS>>>(x, qw, absmax, out, n_tokens);
}